// round 6
// baseline (speedup 1.0000x reference)
#include <cuda_runtime.h>
#include <cuda_bf16.h>
#include <cstdint>

// Problem constants
#define BB    2
#define NQ    4096
#define NS    8
#define NTOT  4104          // NQ + NS
#define CC    192
#define HH    8
#define DD    24            // CC / HH
#define MROWS (BB*NTOT)     // 8208
#define NKP   4352          // padded to 17*256
#define QTILES 17           // q-tiles of 256
#define KTILES 65           // ceil(4104/64)
#define LOG2E 1.4426950408889634f

// ---------------------------------------------------------------------------
// helpers
// ---------------------------------------------------------------------------
__device__ __forceinline__ float ex2f(float x) {
    float r; asm("ex2.approx.f32 %0, %1;" : "=f"(r) : "f"(x)); return r;
}
__device__ __forceinline__ uint32_t cvt_bf2(float hi, float lo) {
    uint32_t r; asm("cvt.rn.bf16x2.f32 %0, %1, %2;" : "=r"(r) : "f"(hi), "f"(lo)); return r;
}
__device__ __forceinline__ void hmma(float (&c)[4],
                                     uint32_t a0, uint32_t a1, uint32_t a2, uint32_t a3,
                                     uint32_t b0, uint32_t b1) {
    asm volatile(
        "mma.sync.aligned.m16n8k16.row.col.f32.bf16.bf16.f32 "
        "{%0,%1,%2,%3},{%4,%5,%6,%7},{%8,%9},{%0,%1,%2,%3};"
        : "+f"(c[0]), "+f"(c[1]), "+f"(c[2]), "+f"(c[3])
        : "r"(a0), "r"(a1), "r"(a2), "r"(a3), "r"(b0), "r"(b1));
}
__device__ __forceinline__ uint32_t smem_u32(const void* p) {
    uint32_t a;
    asm("{ .reg .u64 t; cvta.to.shared.u64 t, %1; cvt.u32.u64 %0, t; }" : "=r"(a) : "l"(p));
    return a;
}
#define CP16(dst, src) \
    asm volatile("cp.async.cg.shared.global [%0], [%1], 16;" :: "r"(dst), "l"(src))
#define CP_COMMIT() asm volatile("cp.async.commit_group;" ::: "memory")
#define CP_WAIT(n)  asm volatile("cp.async.wait_group %0;" :: "n"(n) : "memory")

// ---------------------------------------------------------------------------
// Scratch (device globals; zero-initialized -> padding rows stay 0)
// ---------------------------------------------------------------------------
__device__ __align__(16) __nv_bfloat16 g_Qh[16*NKP*32];
__device__ __align__(16) __nv_bfloat16 g_Ql[16*NKP*32];
__device__ __align__(16) __nv_bfloat16 g_Kh[16*NKP*32];
__device__ __align__(16) __nv_bfloat16 g_Kl[16*NKP*32];
__device__ __align__(16) __nv_bfloat16 g_Vth[16*32*NKP];   // V transposed [bh][d][n]
__device__ __align__(16) __nv_bfloat16 g_Vtl[16*32*NKP];
__device__ __align__(16) float g_O[BB*NTOT*CC];

// ---------------------------------------------------------------------------
// 1) QKV projection (concat fused) + bf16 hi/lo split epilogue.
// ---------------------------------------------------------------------------
__global__ __launch_bounds__(256)
void qkv_gemm_kernel(const float* __restrict__ X,
                     const float* __restrict__ S,
                     const float* __restrict__ W,
                     const float* __restrict__ T) {
    __shared__ float As[16][64];
    __shared__ float Ws[16][64];

    const int tx = threadIdx.x;
    const int ty = threadIdx.y;
    const int t  = ty * 16 + tx;
    const int row0 = blockIdx.x * 64;
    const int col0 = blockIdx.y * 64;

    float acc[4][4];
    #pragma unroll
    for (int i = 0; i < 4; i++)
        #pragma unroll
        for (int j = 0; j < 4; j++) acc[i][j] = 0.f;

    const int lr  = t >> 2;
    const int lc4 = t & 3;

    const float* Arow = nullptr;
    {
        int gr = row0 + lr;
        if (gr < MROWS) {
            int b = (gr >= NTOT) ? 1 : 0;
            int n = gr - b * NTOT;
            if (n < NQ) Arow = X + (size_t)(b * NQ + n) * CC;
            else        Arow = S + (size_t)(b * NS + (n - NQ)) * CC;
        }
    }

    for (int k0 = 0; k0 < CC; k0 += 16) {
        {
            float4 a = make_float4(0.f, 0.f, 0.f, 0.f);
            if (Arow) a = *reinterpret_cast<const float4*>(Arow + k0 + lc4 * 4);
            As[lc4*4+0][lr] = a.x; As[lc4*4+1][lr] = a.y;
            As[lc4*4+2][lr] = a.z; As[lc4*4+3][lr] = a.w;
        }
        {
            float4 w = *reinterpret_cast<const float4*>(&W[(col0 + lr) * CC + k0 + lc4 * 4]);
            Ws[lc4*4+0][lr] = w.x; Ws[lc4*4+1][lr] = w.y;
            Ws[lc4*4+2][lr] = w.z; Ws[lc4*4+3][lr] = w.w;
        }
        __syncthreads();
        #pragma unroll
        for (int kk = 0; kk < 16; ++kk) {
            float4 a = *reinterpret_cast<const float4*>(&As[kk][ty * 4]);
            float4 w = *reinterpret_cast<const float4*>(&Ws[kk][tx * 4]);
            float av[4] = {a.x, a.y, a.z, a.w};
            float wv[4] = {w.x, w.y, w.z, w.w};
            #pragma unroll
            for (int i = 0; i < 4; i++)
                #pragma unroll
                for (int j = 0; j < 4; j++)
                    acc[i][j] = fmaf(av[i], wv[j], acc[i][j]);
        }
        __syncthreads();
    }

    #pragma unroll
    for (int i = 0; i < 4; i++) {
        int m = row0 + ty * 4 + i;
        if (m >= MROWS) continue;
        int b = (m >= NTOT) ? 1 : 0;
        int n = m - b * NTOT;
        #pragma unroll
        for (int j2 = 0; j2 < 4; j2 += 2) {
            int o = col0 + tx * 4 + j2;        // even
            float v0 = acc[i][j2], v1 = acc[i][j2 + 1];
            if (o < CC) {                       // Q: fold temp*log2e, split, packed
                int hh = o / DD, d = o % DD;    // d even, pair same head
                float sc = T[hh] * LOG2E;
                float a0 = v0 * sc, a1 = v1 * sc;
                uint32_t hp = cvt_bf2(a1, a0);
                float r0 = a0 - __uint_as_float(hp << 16);
                float r1 = a1 - __uint_as_float(hp & 0xffff0000u);
                uint32_t lp = cvt_bf2(r1, r0);
                size_t idx = ((size_t)(b * HH + hh) * NKP + n) * 32 + d;
                *reinterpret_cast<uint32_t*>(&g_Qh[idx]) = hp;
                *reinterpret_cast<uint32_t*>(&g_Ql[idx]) = lp;
            } else if (o < 2 * CC) {            // K: split, packed
                int oo = o - CC, hh = oo / DD, d = oo % DD;
                uint32_t hp = cvt_bf2(v1, v0);
                float r0 = v0 - __uint_as_float(hp << 16);
                float r1 = v1 - __uint_as_float(hp & 0xffff0000u);
                uint32_t lp = cvt_bf2(r1, r0);
                size_t idx = ((size_t)(b * HH + hh) * NKP + n) * 32 + d;
                *reinterpret_cast<uint32_t*>(&g_Kh[idx]) = hp;
                *reinterpret_cast<uint32_t*>(&g_Kl[idx]) = lp;
            } else {                            // V: split, transposed (scalar)
                int oo = o - 2 * CC, hh = oo / DD, d = oo % DD;
                #pragma unroll
                for (int u = 0; u < 2; u++) {
                    float val = (u == 0) ? v0 : v1;
                    __nv_bfloat16 hi = __float2bfloat16_rn(val);
                    __nv_bfloat16 lo = __float2bfloat16_rn(val - __bfloat162float(hi));
                    size_t idx = ((size_t)(b * HH + hh) * 32 + d + u) * NKP + n;
                    g_Vth[idx] = hi; g_Vtl[idx] = lo;
                }
            }
        }
    }
}

// ---------------------------------------------------------------------------
// 2) Attention: flash, mma.sync bf16 hi/lo split, cp.async double buffering.
//    CTA = 256 threads (8 warps), 256 queries; loop 65 key-tiles of 64.
// Dynamic smem layout (bytes):
//   0      : Qh 256x80               20480
//   20480  : Ql 256x80               20480
//   40960 + s*27648 (s=0,1):
//     +0     Kh 64x80                 5120
//     +5120  Kl 64x80                 5120
//     +10240 Vh 32x272                8704
//     +18944 Vl 32x272                8704
// total 96256
// ---------------------------------------------------------------------------
#define OQH 0
#define OQL 20480
#define OKV 40960
#define STG 27648
#define OKH 0
#define OKL 5120
#define OVH 10240
#define OVL 18944
#define ATT_SMEM 96256

__global__ __launch_bounds__(256)
void attn_kernel() {
    extern __shared__ __align__(16) uint8_t dsm[];
    const uint32_t sb = smem_u32(dsm);

    const int tid = threadIdx.x;
    const int w   = tid >> 5;
    const int t   = tid & 31;
    const int bh  = blockIdx.z * HH + blockIdx.y;
    const int q0  = blockIdx.x * 256;

    // ---- issue Q loads (8 x cp.async) + tile 0 K/V ----
    {
        const __nv_bfloat16* qh = g_Qh + ((size_t)bh * NKP + q0 + tid) * 32;
        const __nv_bfloat16* ql = g_Ql + ((size_t)bh * NKP + q0 + tid) * 32;
        #pragma unroll
        for (int g = 0; g < 4; g++) {
            CP16(sb + OQH + tid * 80 + g * 16, qh + g * 8);
            CP16(sb + OQL + tid * 80 + g * 16, ql + g * 8);
        }
    }
    const int kkey = tid >> 2, kg = tid & 3;
    const int vd   = tid >> 3, vg = tid & 7;
    {
        const uint32_t kb = sb + OKV;
        CP16(kb + OKH + kkey * 80 + kg * 16, g_Kh + ((size_t)bh * NKP + kkey) * 32 + kg * 8);
        CP16(kb + OKL + kkey * 80 + kg * 16, g_Kl + ((size_t)bh * NKP + kkey) * 32 + kg * 8);
        CP16(kb + OVH + vd * 272 + vg * 16, g_Vth + ((size_t)bh * 32 + vd) * NKP + vg * 8);
        CP16(kb + OVL + vd * 272 + vg * 16, g_Vtl + ((size_t)bh * 32 + vd) * NKP + vg * 8);
    }
    CP_COMMIT();

    uint32_t aQ[2][2][2][4];
    float O[2][3][4];
    float lsum[2][2];
    #pragma unroll
    for (int mt = 0; mt < 2; mt++) {
        lsum[mt][0] = 0.f; lsum[mt][1] = 0.f;
        #pragma unroll
        for (int nt = 0; nt < 3; nt++)
            #pragma unroll
            for (int c = 0; c < 4; c++) O[mt][nt][c] = 0.f;
    }

    for (int kt = 0; kt < KTILES; ++kt) {
        if (kt + 1 < KTILES) {
            const int j1 = (kt + 1) * 64;
            const uint32_t kb = sb + OKV + ((kt + 1) & 1) * STG;
            CP16(kb + OKH + kkey * 80 + kg * 16, g_Kh + ((size_t)bh * NKP + j1 + kkey) * 32 + kg * 8);
            CP16(kb + OKL + kkey * 80 + kg * 16, g_Kl + ((size_t)bh * NKP + j1 + kkey) * 32 + kg * 8);
            CP16(kb + OVH + vd * 272 + vg * 16, g_Vth + ((size_t)bh * 32 + vd) * NKP + j1 + vg * 8);
            CP16(kb + OVL + vd * 272 + vg * 16, g_Vtl + ((size_t)bh * 32 + vd) * NKP + j1 + vg * 8);
            CP_COMMIT();
            CP_WAIT(1);
        } else {
            CP_WAIT(0);
        }
        __syncthreads();

        if (kt == 0) {
            // preload Q A-fragments (Q arrived with group 0)
            #pragma unroll
            for (int mt = 0; mt < 2; mt++) {
                int r = w * 32 + mt * 16 + (t >> 2);
                #pragma unroll
                for (int s = 0; s < 2; s++) {
                    int off = s * 32 + (t & 3) * 4;
                    const uint8_t* qh = dsm + OQH + r * 80 + off;
                    const uint8_t* ql = dsm + OQL + r * 80 + off;
                    aQ[0][s][mt][0] = *reinterpret_cast<const uint32_t*>(qh);
                    aQ[0][s][mt][1] = *reinterpret_cast<const uint32_t*>(qh + 8 * 80);
                    aQ[0][s][mt][2] = *reinterpret_cast<const uint32_t*>(qh + 16);
                    aQ[0][s][mt][3] = *reinterpret_cast<const uint32_t*>(qh + 8 * 80 + 16);
                    aQ[1][s][mt][0] = *reinterpret_cast<const uint32_t*>(ql);
                    aQ[1][s][mt][1] = *reinterpret_cast<const uint32_t*>(ql + 8 * 80);
                    aQ[1][s][mt][2] = *reinterpret_cast<const uint32_t*>(ql + 16);
                    aQ[1][s][mt][3] = *reinterpret_cast<const uint32_t*>(ql + 8 * 80 + 16);
                }
            }
        }

        const uint8_t* kb  = dsm + OKV + (kt & 1) * STG;
        const uint8_t* sKh = kb + OKH;
        const uint8_t* sKl = kb + OKL;
        const uint8_t* sVh = kb + OVH;
        const uint8_t* sVl = kb + OVL;
        const int j0 = kt * 64;

        // ---- S = qh*kh + ql*kh + qh*kl ----
        float C[2][8][4];
        #pragma unroll
        for (int mt = 0; mt < 2; mt++)
            #pragma unroll
            for (int nt = 0; nt < 8; nt++)
                #pragma unroll
                for (int c = 0; c < 4; c++) C[mt][nt][c] = 0.f;

        #pragma unroll
        for (int c3 = 0; c3 < 3; c3++) {
            const uint8_t* bB = (c3 == 2) ? sKl : sKh;
            const int aI = (c3 == 1) ? 1 : 0;
            #pragma unroll
            for (int s = 0; s < 2; s++) {
                uint32_t b0[8], b1[8];
                #pragma unroll
                for (int nt = 0; nt < 8; nt++) {
                    const uint8_t* p = bB + (nt * 8 + (t >> 2)) * 80 + s * 32 + (t & 3) * 4;
                    b0[nt] = *reinterpret_cast<const uint32_t*>(p);
                    b1[nt] = *reinterpret_cast<const uint32_t*>(p + 16);
                }
                #pragma unroll
                for (int nt = 0; nt < 8; nt++)
                    #pragma unroll
                    for (int mt = 0; mt < 2; mt++)
                        hmma(C[mt][nt], aQ[aI][s][mt][0], aQ[aI][s][mt][1],
                             aQ[aI][s][mt][2], aQ[aI][s][mt][3], b0[nt], b1[nt]);
            }
        }

        // ---- softmax + split P to bf16 hi/lo ----
        uint32_t PH[2][4][4], PL[2][4][4];
        const bool edge = (j0 + 64 > NTOT);
        #pragma unroll
        for (int mt = 0; mt < 2; mt++) {
            #pragma unroll
            for (int nt = 0; nt < 8; nt++) {
                float p0 = ex2f(C[mt][nt][0]);
                float p1 = ex2f(C[mt][nt][1]);
                float p2 = ex2f(C[mt][nt][2]);
                float p3 = ex2f(C[mt][nt][3]);
                if (edge) {
                    int key0 = j0 + nt * 8 + (t & 3) * 2;
                    if (key0     >= NTOT) { p0 = 0.f; p2 = 0.f; }
                    if (key0 + 1 >= NTOT) { p1 = 0.f; p3 = 0.f; }
                }
                lsum[mt][0] += p0 + p1;
                lsum[mt][1] += p2 + p3;
                uint32_t h01 = cvt_bf2(p1, p0);
                float r0 = p0 - __uint_as_float(h01 << 16);
                float r1 = p1 - __uint_as_float(h01 & 0xffff0000u);
                uint32_t l01 = cvt_bf2(r1, r0);
                uint32_t h23 = cvt_bf2(p3, p2);
                float r2 = p2 - __uint_as_float(h23 << 16);
                float r3 = p3 - __uint_as_float(h23 & 0xffff0000u);
                uint32_t l23 = cvt_bf2(r3, r2);
                int ks = nt >> 1, half = nt & 1;
                PH[mt][ks][half * 2 + 0] = h01;
                PH[mt][ks][half * 2 + 1] = h23;
                PL[mt][ks][half * 2 + 0] = l01;
                PL[mt][ks][half * 2 + 1] = l23;
            }
        }

        // ---- O += ph*vh + ph*vl + pl*vh ----
        #pragma unroll
        for (int ks = 0; ks < 4; ks++) {
            uint32_t vh0[3], vh1[3], vl0[3], vl1[3];
            #pragma unroll
            for (int nt = 0; nt < 3; nt++) {
                const uint8_t* ph_ = sVh + (nt * 8 + (t >> 2)) * 272 + ks * 32 + (t & 3) * 4;
                const uint8_t* pl_ = sVl + (nt * 8 + (t >> 2)) * 272 + ks * 32 + (t & 3) * 4;
                vh0[nt] = *reinterpret_cast<const uint32_t*>(ph_);
                vh1[nt] = *reinterpret_cast<const uint32_t*>(ph_ + 16);
                vl0[nt] = *reinterpret_cast<const uint32_t*>(pl_);
                vl1[nt] = *reinterpret_cast<const uint32_t*>(pl_ + 16);
            }
            #pragma unroll
            for (int nt = 0; nt < 3; nt++)
                #pragma unroll
                for (int mt = 0; mt < 2; mt++)
                    hmma(O[mt][nt], PH[mt][ks][0], PH[mt][ks][1], PH[mt][ks][2], PH[mt][ks][3],
                         vh0[nt], vh1[nt]);
            #pragma unroll
            for (int nt = 0; nt < 3; nt++)
                #pragma unroll
                for (int mt = 0; mt < 2; mt++)
                    hmma(O[mt][nt], PH[mt][ks][0], PH[mt][ks][1], PH[mt][ks][2], PH[mt][ks][3],
                         vl0[nt], vl1[nt]);
            #pragma unroll
            for (int nt = 0; nt < 3; nt++)
                #pragma unroll
                for (int mt = 0; mt < 2; mt++)
                    hmma(O[mt][nt], PL[mt][ks][0], PL[mt][ks][1], PL[mt][ks][2], PL[mt][ks][3],
                         vh0[nt], vh1[nt]);
        }
        __syncthreads();
    }

    // ---- reduce row sums over quad lanes, invert ----
    #pragma unroll
    for (int mt = 0; mt < 2; mt++)
        #pragma unroll
        for (int hf = 0; hf < 2; hf++) {
            float v = lsum[mt][hf];
            v += __shfl_xor_sync(0xffffffffu, v, 1);
            v += __shfl_xor_sync(0xffffffffu, v, 2);
            lsum[mt][hf] = 1.f / v;
        }

    // ---- epilogue: O / l -> g_O ----
    #pragma unroll
    for (int mt = 0; mt < 2; mt++) {
        #pragma unroll
        for (int c = 0; c < 4; c++) {
            int row = w * 32 + mt * 16 + (t >> 2) + ((c >> 1) ? 8 : 0);
            int q = q0 + row;
            if (q < NTOT) {
                float inv = lsum[mt][c >> 1];
                #pragma unroll
                for (int nt = 0; nt < 3; nt++) {
                    int d = blockIdx.y * DD + nt * 8 + (t & 3) * 2 + (c & 1);
                    g_O[(size_t)(blockIdx.z * NTOT + q) * CC + d] = O[mt][nt][c] * inv;
                }
            }
        }
    }
}

// ---------------------------------------------------------------------------
// 3) Output projection: out[b,n,o] = sum_c O[b,n,c] * Wout[o,c], n < NQ only.
// ---------------------------------------------------------------------------
__global__ __launch_bounds__(256)
void out_gemm_kernel(const float* __restrict__ W, float* __restrict__ out) {
    __shared__ float As[16][64];
    __shared__ float Ws[16][64];

    const int tx = threadIdx.x;
    const int ty = threadIdx.y;
    const int t  = ty * 16 + tx;
    const int row0 = blockIdx.x * 64;
    const int col0 = blockIdx.y * 64;

    float acc[4][4];
    #pragma unroll
    for (int i = 0; i < 4; i++)
        #pragma unroll
        for (int j = 0; j < 4; j++) acc[i][j] = 0.f;

    const int lr  = t >> 2;
    const int lc4 = t & 3;

    for (int k0 = 0; k0 < CC; k0 += 16) {
        {
            int m = row0 + lr;
            int b = m >> 12;
            int n = m & 4095;
            float4 a = *reinterpret_cast<const float4*>(
                &g_O[(size_t)(b * NTOT + n) * CC + k0 + lc4 * 4]);
            As[lc4*4+0][lr] = a.x; As[lc4*4+1][lr] = a.y;
            As[lc4*4+2][lr] = a.z; As[lc4*4+3][lr] = a.w;
        }
        {
            float4 w = *reinterpret_cast<const float4*>(&W[(col0 + lr) * CC + k0 + lc4 * 4]);
            Ws[lc4*4+0][lr] = w.x; Ws[lc4*4+1][lr] = w.y;
            Ws[lc4*4+2][lr] = w.z; Ws[lc4*4+3][lr] = w.w;
        }
        __syncthreads();
        #pragma unroll
        for (int kk = 0; kk < 16; ++kk) {
            float4 a = *reinterpret_cast<const float4*>(&As[kk][ty * 4]);
            float4 w = *reinterpret_cast<const float4*>(&Ws[kk][tx * 4]);
            float av[4] = {a.x, a.y, a.z, a.w};
            float wv[4] = {w.x, w.y, w.z, w.w};
            #pragma unroll
            for (int i = 0; i < 4; i++)
                #pragma unroll
                for (int j = 0; j < 4; j++)
                    acc[i][j] = fmaf(av[i], wv[j], acc[i][j]);
        }
        __syncthreads();
    }

    #pragma unroll
    for (int i = 0; i < 4; i++) {
        int m = row0 + ty * 4 + i;
        #pragma unroll
        for (int j = 0; j < 4; j++) {
            int o = col0 + tx * 4 + j;
            out[(size_t)m * CC + o] = acc[i][j];
        }
    }
}

// ---------------------------------------------------------------------------
// launch
// ---------------------------------------------------------------------------
extern "C" void kernel_launch(void* const* d_in, const int* in_sizes, int n_in,
                              void* d_out, int out_size) {
    const float* X  = nullptr;
    const float* S  = nullptr;
    const float* Wq = nullptr;
    const float* Wo = nullptr;
    const float* T  = nullptr;
    for (int i = 0; i < n_in; i++) {
        switch (in_sizes[i]) {
            case BB * NQ * CC:  X  = (const float*)d_in[i]; break;
            case BB * NS * CC:  S  = (const float*)d_in[i]; break;
            case 3 * CC * CC:   Wq = (const float*)d_in[i]; break;
            case CC * CC:       Wo = (const float*)d_in[i]; break;
            case HH:            T  = (const float*)d_in[i]; break;
        }
    }

    // 1) QKV projection (concat fused, split epilogue)
    {
        dim3 grid((MROWS + 63) / 64, (3 * CC) / 64);   // (129, 9)
        dim3 blk(16, 16);
        qkv_gemm_kernel<<<grid, blk>>>(X, S, Wq, T);
    }
    // 2) attention (mma.sync bf16 split, cp.async pipelined)
    {
        static int att_init = 0;
        if (!att_init) {
            cudaFuncSetAttribute(attn_kernel, cudaFuncAttributeMaxDynamicSharedMemorySize, ATT_SMEM);
            att_init = 1;
        }
        dim3 grid(QTILES, HH, BB);                      // (17, 8, 2)
        attn_kernel<<<grid, 256, ATT_SMEM>>>();
    }
    // 3) output projection
    {
        dim3 grid((BB * NQ) / 64, CC / 64);             // (128, 3)
        dim3 blk(16, 16);
        out_gemm_kernel<<<grid, blk>>>(Wo, (float*)d_out);
    }
}